// round 14
// baseline (speedup 1.0000x reference)
#include <cuda_runtime.h>
#include <cuda_fp16.h>
#include <math.h>
#include <stdint.h>

#define NN 30000
#define EE 480000
#define ET (EE + NN)
#define GG 30
#define FH 512
#define DHD 64
#define MAXDEG 128
#define PADDEG 132

// ---------------- scratch (static device globals; no allocation) ----------------
__device__ __half2 g_hh  [(size_t)NN * (FH / 2)];  // fp16 features (gather path)
__device__ __half  g_ah  [(size_t)NN * FH];        // fp16 GEMM A operand / layer outputs
__device__ __half2 g_aggh[(size_t)NN * (FH / 2)];  // fp16 aggregation output (pre-BN)
__device__ __half  g_w0t[256 * 512];               // W0^T fp16 [F][K]
__device__ __half  g_w1t[512 * 512];
__device__ __half  g_w2t[512 * 64];
__device__ float   g_ssrc[NN * 8];
__device__ float   g_sdst[NN * 8];
__device__ float   g_alpha[(size_t)8 * ET];        // deg>MAXDEG fallback only
__device__ int     g_rowptr[NN + 1];
__device__ int     g_cursor[NN];
__device__ int     g_esrc[ET];
__device__ double  g_sum[FH];
__device__ double  g_sumsq[FH];
__device__ float   g_pool[GG * DHD];
__device__ int     g_cnt[GG];
__device__ int     g_is64;

__device__ __forceinline__ __half* sel_w(int s) {
    return (s == 0) ? g_w0t : (s == 1 ? g_w1t : g_w2t);
}

__device__ __forceinline__ int idx_at(const void* p, size_t i) {
    if (g_is64) return (int)((const long long*)p)[i];
    return ((const int*)p)[i];
}

// ---------------- dtype detection ----------------
__global__ void detect_dtype(const void* ei) {
    const long long* p64 = (const long long*)ei;
    long long v = p64[threadIdx.x];
    int bad = (v < 0 || v >= NN) ? 1 : 0;
    int any = __syncthreads_or(bad);
    if (threadIdx.x == 0) g_is64 = any ? 0 : 1;
}

// ---------------- fp16 conversions ----------------
__global__ void cvt_x(const float* __restrict__ x) {
    int i = blockIdx.x * blockDim.x + threadIdx.x;     // over NN*256/4
    if (i >= NN * 256 / 4) return;
    float4 v = reinterpret_cast<const float4*>(x)[i];
    __half2* o = reinterpret_cast<__half2*>(g_ah);
    o[i * 2]     = __floats2half2_rn(v.x, v.y);
    o[i * 2 + 1] = __floats2half2_rn(v.z, v.w);
}

__global__ void cvt_w(const float* __restrict__ W, int Wsel, int K, int F) {
    int idx = blockIdx.x * blockDim.x + threadIdx.x;
    if (idx >= K * F) return;
    int k = idx / F, f = idx % F;
    sel_w(Wsel)[(size_t)f * K + k] = __float2half(W[idx]);
}

// ---------------- CSR build ----------------
__global__ void csr_init() {
    int i = blockIdx.x * blockDim.x + threadIdx.x;
    if (i < NN) g_cursor[i] = 1;   // self-loop
}

__global__ void csr_count(const void* __restrict__ ei) {
    int e = blockIdx.x * blockDim.x + threadIdx.x;
    if (e < EE) atomicAdd(&g_cursor[idx_at(ei, (size_t)EE + e)], 1);
}

__global__ void csr_scan() {
    __shared__ int warp_pref[32];
    const int CH = 30;
    int t = threadIdx.x, lane = t & 31, wid = t >> 5;
    int base = t * CH;
    int local[CH];
    int s = 0;
#pragma unroll
    for (int i = 0; i < CH; i++) {
        int idx = base + i;
        int v = (idx < NN) ? g_cursor[idx] : 0;
        local[i] = s;
        s += v;
    }
    int inc = s;
#pragma unroll
    for (int o = 1; o < 32; o <<= 1) {
        int u = __shfl_up_sync(0xffffffffu, inc, o);
        if (lane >= o) inc += u;
    }
    if (lane == 31) warp_pref[wid] = inc;
    __syncthreads();
    if (wid == 0) {
        int w = warp_pref[lane];
#pragma unroll
        for (int o = 1; o < 32; o <<= 1) {
            int u = __shfl_up_sync(0xffffffffu, w, o);
            if (lane >= o) w += u;
        }
        warp_pref[lane] = w;
    }
    __syncthreads();
    int offset = (inc - s) + (wid > 0 ? warp_pref[wid - 1] : 0);
#pragma unroll
    for (int i = 0; i < CH; i++) {
        int idx = base + i;
        if (idx < NN) {
            int v = offset + local[i];
            g_rowptr[idx] = v;
            g_cursor[idx] = v;
        }
    }
    if (t == 1023) g_rowptr[NN] = offset + s;
}

__global__ void csr_scatter(const void* __restrict__ ei) {
    int e = blockIdx.x * blockDim.x + threadIdx.x;
    if (e < EE) {
        int d = idx_at(ei, (size_t)EE + e);
        int p = atomicAdd(&g_cursor[d], 1);
        g_esrc[p] = idx_at(ei, (size_t)e);
    } else if (e < ET) {
        int n = e - EE;
        int p = atomicAdd(&g_cursor[n], 1);
        g_esrc[p] = n;
    }
}

// --------- fp16 m16n8k16 tensor GEMM + fused score epilogue, cp.async 2-stage ----
#define BM 128
#define BN 64
#define BKH 32          // K halves per tile
#define APD 20          // half2 row stride (16 data + 4 pad)

__device__ __forceinline__ void cp16(uint32_t dst, const void* src, int valid) {
    int sz = valid ? 16 : 0;
    asm volatile("cp.async.ca.shared.global [%0], [%1], 16, %2;\n"
                 :: "r"(dst), "l"(src), "r"(sz));
}
__device__ __forceinline__ void cp_commit() {
    asm volatile("cp.async.commit_group;\n");
}
template <int N>
__device__ __forceinline__ void cp_wait() {
    asm volatile("cp.async.wait_group %0;\n" :: "n"(N));
}

__device__ __forceinline__ void mma_f16(float* c, uint32_t a0, uint32_t a1,
                                        uint32_t a2, uint32_t a3,
                                        uint32_t b0, uint32_t b1) {
    asm volatile(
        "mma.sync.aligned.m16n8k16.row.col.f32.f16.f16.f32 "
        "{%0,%1,%2,%3}, {%4,%5,%6,%7}, {%8,%9}, {%0,%1,%2,%3};"
        : "+f"(c[0]), "+f"(c[1]), "+f"(c[2]), "+f"(c[3])
        : "r"(a0), "r"(a1), "r"(a2), "r"(a3), "r"(b0), "r"(b1));
}

// A = g_ah [M][K] fp16, B = Wt [F][K] fp16 (transposed). Outputs g_hh + scores.
__global__ __launch_bounds__(256) void gemm_fp16(int Bsel,
                                                 const float* __restrict__ avS,
                                                 const float* __restrict__ avD,
                                                 int M, int K, int F, int heads) {
    const __half* __restrict__ A = g_ah;
    const __half* __restrict__ Bw = sel_w(Bsel);
    __shared__ __half2 As[2][BM * APD];
    __shared__ __half2 Bs[2][64 * APD];
    __shared__ float sS[BM], sD[BM];

    int tid = threadIdx.x;
    int lane = tid & 31, wid = tid >> 5;
    int gid = lane >> 2, tig = lane & 3;
    int wm = (wid & 3) * 32;
    int wn = (wid >> 2) * 32;
    int row0 = blockIdx.y * BM, col0 = blockIdx.x * BN;
    int hh = blockIdx.x;                 // BN == DHD: one head per block column

    for (int i = tid; i < BM; i += 256) { sS[i] = 0.f; sD[i] = 0.f; }

    uint32_t sA[2], sB[2];
    sA[0] = (uint32_t)__cvta_generic_to_shared(&As[0][0]);
    sA[1] = (uint32_t)__cvta_generic_to_shared(&As[1][0]);
    sB[0] = (uint32_t)__cvta_generic_to_shared(&Bs[0][0]);
    sB[1] = (uint32_t)__cvta_generic_to_shared(&Bs[1][0]);

    int KT = K / BKH;
    float acc[2][4][4];
#pragma unroll
    for (int mt = 0; mt < 2; mt++)
#pragma unroll
        for (int nt = 0; nt < 4; nt++)
#pragma unroll
            for (int j = 0; j < 4; j++) acc[mt][nt][j] = 0.f;

    auto load_tile = [&](int buf, int k0) {
#pragma unroll
        for (int t = 0; t < 2; t++) {
            int c = tid + t * 256;
            int r = c >> 2, cc = c & 3;
            int grow = row0 + r;
            int ok = grow < M;
            const __half* src = A + (size_t)(ok ? grow : 0) * K + k0 + cc * 8;
            cp16(sA[buf] + r * (APD * 4) + cc * 16, src, ok);
        }
        int r = tid >> 2, cc = tid & 3;
        const __half* bsrc = Bw + (size_t)(col0 + r) * K + k0 + cc * 8;
        cp16(sB[buf] + r * (APD * 4) + cc * 16, bsrc, 1);
    };

    load_tile(0, 0);
    cp_commit();

    for (int kt = 0; kt < KT; kt++) {
        int buf = kt & 1;
        if (kt + 1 < KT) {
            load_tile(buf ^ 1, (kt + 1) * BKH);
            cp_commit();
            cp_wait<1>();
        } else {
            cp_wait<0>();
        }
        __syncthreads();

        const __half2* Ab = &As[buf][0];
        const __half2* Bb = &Bs[buf][0];
#pragma unroll
        for (int kk = 0; kk < 2; kk++) {
            int kb = kk * 8;
            uint32_t a[2][4];
#pragma unroll
            for (int mt = 0; mt < 2; mt++) {
                int r = wm + mt * 16 + gid;
                a[mt][0] = *reinterpret_cast<const uint32_t*>(&Ab[r * APD + kb + tig]);
                a[mt][1] = *reinterpret_cast<const uint32_t*>(&Ab[(r + 8) * APD + kb + tig]);
                a[mt][2] = *reinterpret_cast<const uint32_t*>(&Ab[r * APD + kb + tig + 4]);
                a[mt][3] = *reinterpret_cast<const uint32_t*>(&Ab[(r + 8) * APD + kb + tig + 4]);
            }
#pragma unroll
            for (int nt = 0; nt < 4; nt++) {
                int n = wn + nt * 8 + gid;
                uint32_t b0 = *reinterpret_cast<const uint32_t*>(&Bb[n * APD + kb + tig]);
                uint32_t b1 = *reinterpret_cast<const uint32_t*>(&Bb[n * APD + kb + tig + 4]);
#pragma unroll
                for (int mt = 0; mt < 2; mt++)
                    mma_f16(acc[mt][nt], a[mt][0], a[mt][1], a[mt][2], a[mt][3], b0, b1);
            }
        }
        __syncthreads();
    }

    // ---- epilogue: fp16 feature store + fused attention-score reduce ----
    int Fh = F >> 1;
#pragma unroll
    for (int mt = 0; mt < 2; mt++) {
        float pS0 = 0.f, pD0 = 0.f, pS1 = 0.f, pD1 = 0.f;
#pragma unroll
        for (int nt = 0; nt < 4; nt++) {
            int cl = wn + nt * 8 + tig * 2;
            int c = col0 + cl;
            float a0s = avS[hh * DHD + cl], a1s = avS[hh * DHD + cl + 1];
            float a0d = avD[hh * DHD + cl], a1d = avD[hh * DHD + cl + 1];
            int r = row0 + wm + mt * 16 + gid;
            if (r < M)
                g_hh[(size_t)r * Fh + (c >> 1)] =
                    __floats2half2_rn(acc[mt][nt][0], acc[mt][nt][1]);
            pS0 += acc[mt][nt][0] * a0s + acc[mt][nt][1] * a1s;
            pD0 += acc[mt][nt][0] * a0d + acc[mt][nt][1] * a1d;
            int r2 = r + 8;
            if (r2 < M)
                g_hh[(size_t)r2 * Fh + (c >> 1)] =
                    __floats2half2_rn(acc[mt][nt][2], acc[mt][nt][3]);
            pS1 += acc[mt][nt][2] * a0s + acc[mt][nt][3] * a1s;
            pD1 += acc[mt][nt][2] * a0d + acc[mt][nt][3] * a1d;
        }
        int rl = wm + mt * 16 + gid;
        atomicAdd(&sS[rl], pS0);
        atomicAdd(&sD[rl], pD0);
        atomicAdd(&sS[rl + 8], pS1);
        atomicAdd(&sD[rl + 8], pD1);
    }
    __syncthreads();
    if (tid < BM) {
        int r = row0 + tid;
        if (r < M) {
            g_ssrc[r * heads + hh] = sS[tid];
            g_sdst[r * heads + hh] = sD[tid];
        }
    }
}

// ------- fused softmax + aggregation, 8 heads, block per node, fp16 output -------
__global__ __launch_bounds__(256) void gat_softagg8(const float* __restrict__ bias) {
    __shared__ int   ssm[MAXDEG];
    __shared__ float esm[8 * PADDEG];     // [head][edge]
    __shared__ float sd_sm[8];
    int n = blockIdx.x;
    int tid = threadIdx.x, lane = tid & 31, wid = tid >> 5;   // wid = head
    int half = lane >> 4, l16 = lane & 15;
    int beg = g_rowptr[n];
    int deg = g_rowptr[n + 1] - beg;

    if (deg <= MAXDEG) {
        if (tid < 8) sd_sm[tid] = g_sdst[n * 8 + tid];
        for (int i = tid; i < deg; i += 256) ssm[i] = g_esrc[beg + i];
        __syncthreads();
        for (int i = tid; i < deg * 8; i += 256) {
            int e = i >> 3, h = i & 7;
            float v = g_ssrc[ssm[e] * 8 + h] + sd_sm[h];
            v = v > 0.f ? v : 0.2f * v;
            esm[h * PADDEG + e] = v;
        }
        __syncthreads();
        float* ep = &esm[wid * PADDEG];
        float m = -1e30f;
        for (int i = lane; i < deg; i += 32) m = fmaxf(m, ep[i]);
#pragma unroll
        for (int o = 16; o; o >>= 1) m = fmaxf(m, __shfl_xor_sync(0xffffffffu, m, o));
        float sum = 0.f;
        for (int i = lane; i < deg; i += 32) {
            float ex = __expf(ep[i] - m);
            ep[i] = ex;
            sum += ex;
        }
#pragma unroll
        for (int o = 16; o; o >>= 1) sum += __shfl_xor_sync(0xffffffffu, sum, o);
        float inv = 1.f / (sum + 1e-16f);
        __syncwarp();
        float a0 = 0.f, a1 = 0.f, a2 = 0.f, a3 = 0.f;
#pragma unroll 2
        for (int i = half; i < deg; i += 2) {
            int s = ssm[i];
            float al = ep[i];
            const uint2 u = *reinterpret_cast<const uint2*>(
                &g_hh[(size_t)s * 256 + wid * 32 + l16 * 2]);
            float2 v0 = __half22float2(*reinterpret_cast<const __half2*>(&u.x));
            float2 v1 = __half22float2(*reinterpret_cast<const __half2*>(&u.y));
            a0 += al * v0.x; a1 += al * v0.y;
            a2 += al * v1.x; a3 += al * v1.y;
        }
        a0 += __shfl_xor_sync(0xffffffffu, a0, 16);
        a1 += __shfl_xor_sync(0xffffffffu, a1, 16);
        a2 += __shfl_xor_sync(0xffffffffu, a2, 16);
        a3 += __shfl_xor_sync(0xffffffffu, a3, 16);
        if (half == 0) {
            int cb = wid * DHD + l16 * 4;
            uint2 o;
            __half2 h0 = __floats2half2_rn(a0 * inv + bias[cb],     a1 * inv + bias[cb + 1]);
            __half2 h1 = __floats2half2_rn(a2 * inv + bias[cb + 2], a3 * inv + bias[cb + 3]);
            o.x = *reinterpret_cast<uint32_t*>(&h0);
            o.y = *reinterpret_cast<uint32_t*>(&h1);
            *reinterpret_cast<uint2*>(&g_aggh[(size_t)n * 256 + wid * 32 + l16 * 2]) = o;
        }
    } else {
        float sd = g_sdst[n * 8 + wid];
        float* ap = g_alpha + (size_t)wid * ET;
        float m = -1e30f;
        for (int i = beg + lane; i < beg + deg; i += 32) {
            int s = g_esrc[i];
            float e = g_ssrc[s * 8 + wid] + sd;
            e = e > 0.f ? e : 0.2f * e;
            ap[i] = e;
            m = fmaxf(m, e);
        }
#pragma unroll
        for (int o = 16; o; o >>= 1) m = fmaxf(m, __shfl_xor_sync(0xffffffffu, m, o));
        float sum = 0.f;
        for (int i = beg + lane; i < beg + deg; i += 32) {
            float e = __expf(ap[i] - m);
            ap[i] = e;
            sum += e;
        }
#pragma unroll
        for (int o = 16; o; o >>= 1) sum += __shfl_xor_sync(0xffffffffu, sum, o);
        float inv = 1.f / (sum + 1e-16f);
        float ax = 0.f, ay = 0.f;
        for (int i = beg; i < beg + deg; i++) {
            int s = g_esrc[i];
            float al = ap[i];
            float2 v = __half22float2(g_hh[(size_t)s * 256 + wid * 32 + lane]);
            ax += al * v.x;
            ay += al * v.y;
        }
        g_aggh[(size_t)n * 256 + wid * 32 + lane] =
            __floats2half2_rn(ax * inv + bias[wid * DHD + 2 * lane],
                              ay * inv + bias[wid * DHD + 2 * lane + 1]);
    }
}

// ---------------- single-head softmax+agg (layer 2), warp per node ----------------
__global__ void gat_softagg1(const float* __restrict__ bias) {
    int n = blockIdx.x * blockDim.y + threadIdx.y;
    if (n >= NN) return;
    int lane = threadIdx.x;
    int half = lane >> 4, l16 = lane & 15;
    int beg = g_rowptr[n], end = g_rowptr[n + 1];
    float sd = g_sdst[n];
    float* ap = g_alpha;

    float m = -1e30f;
    for (int i = beg + lane; i < end; i += 32) {
        int s = g_esrc[i];
        float e = g_ssrc[s] + sd;
        e = e > 0.f ? e : 0.2f * e;
        ap[i] = e;
        m = fmaxf(m, e);
    }
#pragma unroll
    for (int o = 16; o; o >>= 1) m = fmaxf(m, __shfl_xor_sync(0xffffffffu, m, o));
    float sum = 0.f;
    for (int i = beg + lane; i < end; i += 32) {
        float e = __expf(ap[i] - m);
        ap[i] = e;
        sum += e;
    }
#pragma unroll
    for (int o = 16; o; o >>= 1) sum += __shfl_xor_sync(0xffffffffu, sum, o);
    float inv = 1.f / (sum + 1e-16f);

    float a0 = 0.f, a1 = 0.f, a2 = 0.f, a3 = 0.f;
#pragma unroll 2
    for (int i = beg + half; i < end; i += 2) {
        int s = g_esrc[i];
        float al = ap[i];
        const uint2 u = *reinterpret_cast<const uint2*>(&g_hh[(size_t)s * 32 + l16 * 2]);
        float2 v0 = __half22float2(*reinterpret_cast<const __half2*>(&u.x));
        float2 v1 = __half22float2(*reinterpret_cast<const __half2*>(&u.y));
        a0 += al * v0.x; a1 += al * v0.y;
        a2 += al * v1.x; a3 += al * v1.y;
    }
    a0 += __shfl_xor_sync(0xffffffffu, a0, 16);
    a1 += __shfl_xor_sync(0xffffffffu, a1, 16);
    a2 += __shfl_xor_sync(0xffffffffu, a2, 16);
    a3 += __shfl_xor_sync(0xffffffffu, a3, 16);
    if (half == 0) {
        int cb = l16 * 4;
        uint2 o;
        __half2 h0 = __floats2half2_rn(a0 * inv + bias[cb],     a1 * inv + bias[cb + 1]);
        __half2 h1 = __floats2half2_rn(a2 * inv + bias[cb + 2], a3 * inv + bias[cb + 3]);
        o.x = *reinterpret_cast<uint32_t*>(&h0);
        o.y = *reinterpret_cast<uint32_t*>(&h1);
        *reinterpret_cast<uint2*>(&g_aggh[(size_t)n * 32 + l16 * 2]) = o;
    }
}

// ---------------- batch norm (fp16 pipeline) ----------------
__global__ void bn_zero(int F) {
    int f = blockIdx.x * blockDim.x + threadIdx.x;
    if (f < F) { g_sum[f] = 0.0; g_sumsq[f] = 0.0; }
}

__global__ void bn_stats(int F) {
    int r0 = blockIdx.x * 64;
    int rend = min(r0 + 64, NN);
    int F2 = F >> 1;
    for (int f2 = threadIdx.x; f2 < F2; f2 += blockDim.x) {
        float s0 = 0.f, q0 = 0.f, s1 = 0.f, q1 = 0.f;
        for (int r = r0; r < rend; r++) {
            float2 v = __half22float2(g_aggh[(size_t)r * F2 + f2]);
            s0 += v.x; q0 += v.x * v.x;
            s1 += v.y; q1 += v.y * v.y;
        }
        atomicAdd(&g_sum[f2 * 2], (double)s0);
        atomicAdd(&g_sumsq[f2 * 2], (double)q0);
        atomicAdd(&g_sum[f2 * 2 + 1], (double)s1);
        atomicAdd(&g_sumsq[f2 * 2 + 1], (double)q1);
    }
}

// y = ELU(BN(g_aggh)) [+ old g_ah residual]; writes g_ah (fp16).
__global__ void bn_apply(const float* __restrict__ gw, const float* __restrict__ bw,
                         int F, int useResid) {
    size_t i4 = (size_t)blockIdx.x * blockDim.x + threadIdx.x;
    size_t total4 = (size_t)NN * F / 4;
    if (i4 >= total4) return;
    size_t i = i4 * 4;           // half index
    int f = (int)(i % F);
    size_t h2 = i / 2;
    uint2 u = *reinterpret_cast<const uint2*>(&g_aggh[h2]);
    float2 v0 = __half22float2(*reinterpret_cast<const __half2*>(&u.x));
    float2 v1 = __half22float2(*reinterpret_cast<const __half2*>(&u.y));
    float vv[4] = {v0.x, v0.y, v1.x, v1.y};
    float oo[4];
#pragma unroll
    for (int j = 0; j < 4; j++) {
        int fj = f + j;
        float mean = (float)(g_sum[fj] * (1.0 / NN));
        float var  = (float)(g_sumsq[fj] * (1.0 / NN)) - mean * mean;
        float y = (vv[j] - mean) * rsqrtf(var + 1e-5f) * gw[fj] + bw[fj];
        oo[j] = y > 0.f ? y : expm1f(y);
    }
    __half2* ap = reinterpret_cast<__half2*>(g_ah);
    if (useResid) {
        uint2 ru = *reinterpret_cast<const uint2*>(&ap[h2]);
        float2 r0 = __half22float2(*reinterpret_cast<const __half2*>(&ru.x));
        float2 r1 = __half22float2(*reinterpret_cast<const __half2*>(&ru.y));
        oo[0] += r0.x; oo[1] += r0.y; oo[2] += r1.x; oo[3] += r1.y;
    }
    uint2 w;
    __half2 h0 = __floats2half2_rn(oo[0], oo[1]);
    __half2 h1 = __floats2half2_rn(oo[2], oo[3]);
    w.x = *reinterpret_cast<uint32_t*>(&h0);
    w.y = *reinterpret_cast<uint32_t*>(&h1);
    *reinterpret_cast<uint2*>(&ap[h2]) = w;
}

// ---------------- layer norm + global mean pool (reads fp16 g_ah) ----------------
__global__ void pool_zero() {
    int i = blockIdx.x * blockDim.x + threadIdx.x;
    if (i < GG * DHD) g_pool[i] = 0.f;
    if (i < GG) g_cnt[i] = 0;
}

__global__ void ln_pool(const float* __restrict__ lg, const float* __restrict__ lb,
                        const void* __restrict__ batch) {
    int n = blockIdx.x * blockDim.y + threadIdx.y;
    if (n >= NN) return;
    int lane = threadIdx.x;
    const __half2* ap = reinterpret_cast<const __half2*>(g_ah);
    float2 v = __half22float2(ap[(size_t)n * 32 + lane]);
    float s = v.x + v.y;
#pragma unroll
    for (int o = 16; o; o >>= 1) s += __shfl_xor_sync(0xffffffffu, s, o);
    float mean = s * (1.f / 64.f);
    float d0 = v.x - mean, d1 = v.y - mean;
    float q = d0 * d0 + d1 * d1;
#pragma unroll
    for (int o = 16; o; o >>= 1) q += __shfl_xor_sync(0xffffffffu, q, o);
    float r = rsqrtf(q * (1.f / 64.f) + 1e-5f);
    float y0 = d0 * r * lg[lane * 2] + lb[lane * 2];
    float y1 = d1 * r * lg[lane * 2 + 1] + lb[lane * 2 + 1];
    int g = idx_at(batch, (size_t)n);
    atomicAdd(&g_pool[g * 64 + lane * 2], y0);
    atomicAdd(&g_pool[g * 64 + lane * 2 + 1], y1);
    if (lane == 0) atomicAdd(&g_cnt[g], 1);
}

// ---------------- MLP head + log_softmax ----------------
__global__ void head_kernel(const float* __restrict__ fc1w, const float* __restrict__ fc1b,
                            const float* __restrict__ fc2w, const float* __restrict__ fc2b,
                            float* __restrict__ out) {
    int t = threadIdx.x;
    if (t >= GG) return;
    float inv = 1.f / fmaxf((float)g_cnt[t], 1.f);
    float p[64];
#pragma unroll
    for (int f = 0; f < 64; f++) p[f] = g_pool[t * 64 + f] * inv;
    float l0 = fc2b[0], l1 = fc2b[1];
    for (int j = 0; j < 32; j++) {
        float s = fc1b[j];
#pragma unroll
        for (int f = 0; f < 64; f++) s += p[f] * fc1w[f * 32 + j];
        s = s > 0.f ? s : expm1f(s);
        l0 += s * fc2w[j * 2 + 0];
        l1 += s * fc2w[j * 2 + 1];
    }
    float mx = fmaxf(l0, l1);
    float lse = mx + logf(expf(l0 - mx) + expf(l1 - mx));
    out[t * 2 + 0] = l0 - lse;
    out[t * 2 + 1] = l1 - lse;
}

// ---------------- launch ----------------
extern "C" void kernel_launch(void* const* d_in, const int* in_sizes, int n_in,
                              void* d_out, int out_size) {
    const float* x     = (const float*)d_in[0];
    const void*  ei    = d_in[1];
    const void*  batch = d_in[2];
    const float *W0 = (const float*)d_in[3],  *as0 = (const float*)d_in[4],
                *ad0 = (const float*)d_in[5], *b0  = (const float*)d_in[6];
    const float *W1 = (const float*)d_in[7],  *as1 = (const float*)d_in[8],
                *ad1 = (const float*)d_in[9], *b1  = (const float*)d_in[10];
    const float *W2 = (const float*)d_in[11], *as2 = (const float*)d_in[12],
                *ad2 = (const float*)d_in[13], *b2 = (const float*)d_in[14];
    const float *bn0g = (const float*)d_in[15], *bn0b = (const float*)d_in[16];
    const float *bn1g = (const float*)d_in[17], *bn1b = (const float*)d_in[18];
    const float *bn2g = (const float*)d_in[19], *bn2b = (const float*)d_in[20];
    const float *lng  = (const float*)d_in[21], *lnb  = (const float*)d_in[22];
    const float *fc1w = (const float*)d_in[23], *fc1b = (const float*)d_in[24];
    const float *fc2w = (const float*)d_in[25], *fc2b = (const float*)d_in[26];
    float* out = (float*)d_out;

    static cudaStream_t s2 = 0;
    static cudaEvent_t evFork = 0, evJoin = 0;
    static int inited = 0;
    if (!inited) {
        cudaStreamCreateWithFlags(&s2, cudaStreamNonBlocking);
        cudaEventCreateWithFlags(&evFork, cudaEventDisableTiming);
        cudaEventCreateWithFlags(&evJoin, cudaEventDisableTiming);
        inited = 1;
    }

    int gm = (NN + BM - 1) / BM;
    int bnStatGrid = (NN + 63) / 64;

    cudaEventRecord(evFork, 0);
    cudaStreamWaitEvent(s2, evFork, 0);

    cvt_x<<<(NN * 256 / 4 + 255) / 256, 256>>>(x);                 // 1 (main)
    cvt_w<<<(256 * 512 + 255) / 256, 256>>>(W0, 0, 256, 512);      // 2 (main)
    detect_dtype<<<1, 256, 0, s2>>>(ei);                           // 3 (s2)
    gemm_fp16<<<dim3(FH / BN, gm), 256>>>(0, as0, ad0, NN, 256, FH, 8);  // 4 (main)

    csr_init   <<<(NN + 255) / 256, 256, 0, s2>>>();
    csr_count  <<<(EE + 255) / 256, 256, 0, s2>>>(ei);
    cvt_w      <<<(512 * 512 + 255) / 256, 256, 0, s2>>>(W1, 1, 512, 512);
    cvt_w      <<<(512 * 64 + 255) / 256, 256, 0, s2>>>(W2, 2, 512, 64);
    csr_scan   <<<1, 1024, 0, s2>>>();
    csr_scatter<<<(ET + 255) / 256, 256, 0, s2>>>(ei);
    cudaEventRecord(evJoin, s2);
    cudaStreamWaitEvent(0, evJoin, 0);

    // --- layer 0 ---
    gat_softagg8<<<NN, 256>>>(b0);
    bn_zero  <<<(FH + 255) / 256, 256>>>(FH);
    bn_stats <<<bnStatGrid, 256>>>(FH);
    bn_apply <<<(int)(((size_t)NN * FH / 4 + 255) / 256), 256>>>(bn0g, bn0b, FH, 0);

    // --- layer 1: residual (old g_ah = x1) ---
    gemm_fp16<<<dim3(FH / BN, gm), 256>>>(1, as1, ad1, NN, FH, FH, 8);
    gat_softagg8<<<NN, 256>>>(b1);
    bn_zero  <<<(FH + 255) / 256, 256>>>(FH);
    bn_stats <<<bnStatGrid, 256>>>(FH);
    bn_apply <<<(int)(((size_t)NN * FH / 4 + 255) / 256), 256>>>(bn1g, bn1b, FH, 1);

    // --- layer 2: single head ---
    gemm_fp16<<<dim3(1, gm), 256>>>(2, as2, ad2, NN, FH, DHD, 1);
    gat_softagg1<<<(NN + 7) / 8, dim3(32, 8)>>>(b2);
    bn_zero  <<<1, 256>>>(DHD);
    bn_stats <<<bnStatGrid, 256>>>(DHD);
    bn_apply <<<(int)(((size_t)NN * DHD / 4 + 255) / 256), 256>>>(bn2g, bn2b, DHD, 0);

    // --- layer norm + pool + head ---
    pool_zero<<<(GG * DHD + 255) / 256, 256>>>();
    ln_pool<<<(NN + 7) / 8, dim3(32, 8)>>>(lng, lnb, batch);
    head_kernel<<<1, 32>>>(fc1w, fc1b, fc2w, fc2b, out);
}

// round 15
// speedup vs baseline: 1.0465x; 1.0465x over previous
#include <cuda_runtime.h>
#include <cuda_fp16.h>
#include <math.h>
#include <stdint.h>

#define NN 30000
#define EE 480000
#define ET (EE + NN)
#define GG 30
#define FH 512
#define DHD 64
#define MAXDEG 128
#define PADDEG 132

// ---------------- scratch (static device globals; no allocation) ----------------
__device__ __half2 g_hh [(size_t)NN * (FH / 2)];   // fp16 features (gather path)
__device__ __half  g_ah [(size_t)NN * FH];         // fp16 GEMM A operand
__device__ __half  g_w0t[256 * 512];               // W0^T fp16 [F][K]
__device__ __half  g_w1t[512 * 512];
__device__ __half  g_w2t[512 * 64];
__device__ float   g_agg[(size_t)NN * FH];
__device__ float   g_x1 [(size_t)NN * FH];
__device__ float   g_x2 [(size_t)NN * FH];
__device__ float   g_ssrc[NN * 8];
__device__ float   g_sdst[NN * 8];
__device__ float   g_alpha[(size_t)8 * ET];        // deg>MAXDEG fallback only
__device__ int     g_rowptr[NN + 1];
__device__ int     g_cursor[NN];
__device__ int     g_esrc[ET];
__device__ double  g_sum[FH];
__device__ double  g_sumsq[FH];
__device__ float   g_pool[GG * DHD];
__device__ int     g_cnt[GG];
__device__ int     g_is64;

__device__ __forceinline__ float* sel_buf(int s) {
    return (s == 2) ? g_x2 : g_x1;
}
__device__ __forceinline__ __half* sel_w(int s) {
    return (s == 0) ? g_w0t : (s == 1 ? g_w1t : g_w2t);
}

__device__ __forceinline__ int idx_at(const void* p, size_t i) {
    if (g_is64) return (int)((const long long*)p)[i];
    return ((const int*)p)[i];
}

// ---------------- dtype detection ----------------
__global__ void detect_dtype(const void* ei) {
    const long long* p64 = (const long long*)ei;
    long long v = p64[threadIdx.x];
    int bad = (v < 0 || v >= NN) ? 1 : 0;
    int any = __syncthreads_or(bad);
    if (threadIdx.x == 0) g_is64 = any ? 0 : 1;
}

// ---------------- fp16 conversions ----------------
__global__ void cvt_x(const float* __restrict__ x) {
    int i = blockIdx.x * blockDim.x + threadIdx.x;     // over NN*256/4
    if (i >= NN * 256 / 4) return;
    float4 v = reinterpret_cast<const float4*>(x)[i];
    __half2* o = reinterpret_cast<__half2*>(g_ah);
    o[i * 2]     = __floats2half2_rn(v.x, v.y);
    o[i * 2 + 1] = __floats2half2_rn(v.z, v.w);
}

__global__ void cvt_w(const float* __restrict__ W, int Wsel, int K, int F) {
    int idx = blockIdx.x * blockDim.x + threadIdx.x;
    if (idx >= K * F) return;
    int k = idx / F, f = idx % F;
    sel_w(Wsel)[(size_t)f * K + k] = __float2half(W[idx]);
}

// ---------------- CSR build ----------------
__global__ void csr_init() {
    int i = blockIdx.x * blockDim.x + threadIdx.x;
    if (i < NN) g_cursor[i] = 1;   // self-loop
}

__global__ void csr_count(const void* __restrict__ ei) {
    int e = blockIdx.x * blockDim.x + threadIdx.x;
    if (e < EE) atomicAdd(&g_cursor[idx_at(ei, (size_t)EE + e)], 1);
}

__global__ void csr_scan() {
    __shared__ int warp_pref[32];
    const int CH = 30;
    int t = threadIdx.x, lane = t & 31, wid = t >> 5;
    int base = t * CH;
    int local[CH];
    int s = 0;
#pragma unroll
    for (int i = 0; i < CH; i++) {
        int idx = base + i;
        int v = (idx < NN) ? g_cursor[idx] : 0;
        local[i] = s;
        s += v;
    }
    int inc = s;
#pragma unroll
    for (int o = 1; o < 32; o <<= 1) {
        int u = __shfl_up_sync(0xffffffffu, inc, o);
        if (lane >= o) inc += u;
    }
    if (lane == 31) warp_pref[wid] = inc;
    __syncthreads();
    if (wid == 0) {
        int w = warp_pref[lane];
#pragma unroll
        for (int o = 1; o < 32; o <<= 1) {
            int u = __shfl_up_sync(0xffffffffu, w, o);
            if (lane >= o) w += u;
        }
        warp_pref[lane] = w;
    }
    __syncthreads();
    int offset = (inc - s) + (wid > 0 ? warp_pref[wid - 1] : 0);
#pragma unroll
    for (int i = 0; i < CH; i++) {
        int idx = base + i;
        if (idx < NN) {
            int v = offset + local[i];
            g_rowptr[idx] = v;
            g_cursor[idx] = v;
        }
    }
    if (t == 1023) g_rowptr[NN] = offset + s;
}

__global__ void csr_scatter(const void* __restrict__ ei) {
    int e = blockIdx.x * blockDim.x + threadIdx.x;
    if (e < EE) {
        int d = idx_at(ei, (size_t)EE + e);
        int p = atomicAdd(&g_cursor[d], 1);
        g_esrc[p] = idx_at(ei, (size_t)e);
    } else if (e < ET) {
        int n = e - EE;
        int p = atomicAdd(&g_cursor[n], 1);
        g_esrc[p] = n;
    }
}

// --------- fp16 m16n8k16 tensor GEMM + fused score epilogue, cp.async 2-stage ----
#define BM 128
#define BN 64
#define BKH 32          // K halves per tile
#define APD 20          // half2 row stride (16 data + 4 pad)

__device__ __forceinline__ void cp16(uint32_t dst, const void* src, int valid) {
    int sz = valid ? 16 : 0;
    asm volatile("cp.async.ca.shared.global [%0], [%1], 16, %2;\n"
                 :: "r"(dst), "l"(src), "r"(sz));
}
__device__ __forceinline__ void cp_commit() {
    asm volatile("cp.async.commit_group;\n");
}
template <int N>
__device__ __forceinline__ void cp_wait() {
    asm volatile("cp.async.wait_group %0;\n" :: "n"(N));
}

__device__ __forceinline__ void mma_f16(float* c, uint32_t a0, uint32_t a1,
                                        uint32_t a2, uint32_t a3,
                                        uint32_t b0, uint32_t b1) {
    asm volatile(
        "mma.sync.aligned.m16n8k16.row.col.f32.f16.f16.f32 "
        "{%0,%1,%2,%3}, {%4,%5,%6,%7}, {%8,%9}, {%0,%1,%2,%3};"
        : "+f"(c[0]), "+f"(c[1]), "+f"(c[2]), "+f"(c[3])
        : "r"(a0), "r"(a1), "r"(a2), "r"(a3), "r"(b0), "r"(b1));
}

// A = g_ah [M][K] fp16, B = Wt [F][K] fp16 (transposed). Outputs g_hh + scores.
// launch_bounds(256,4): cap regs at 64 -> 4 CTAs/SM (was 74 regs / 3 CTAs, occ 38%).
__global__ __launch_bounds__(256, 4) void gemm_fp16(int Bsel,
                                                    const float* __restrict__ avS,
                                                    const float* __restrict__ avD,
                                                    int M, int K, int F, int heads) {
    const __half* __restrict__ A = g_ah;
    const __half* __restrict__ Bw = sel_w(Bsel);
    __shared__ __half2 As[2][BM * APD];
    __shared__ __half2 Bs[2][64 * APD];
    __shared__ float sS[BM], sD[BM];

    int tid = threadIdx.x;
    int lane = tid & 31, wid = tid >> 5;
    int gid = lane >> 2, tig = lane & 3;
    int wm = (wid & 3) * 32;
    int wn = (wid >> 2) * 32;
    int row0 = blockIdx.y * BM, col0 = blockIdx.x * BN;
    int hh = blockIdx.x;                 // BN == DHD: one head per block column

    for (int i = tid; i < BM; i += 256) { sS[i] = 0.f; sD[i] = 0.f; }

    uint32_t sA[2], sB[2];
    sA[0] = (uint32_t)__cvta_generic_to_shared(&As[0][0]);
    sA[1] = (uint32_t)__cvta_generic_to_shared(&As[1][0]);
    sB[0] = (uint32_t)__cvta_generic_to_shared(&Bs[0][0]);
    sB[1] = (uint32_t)__cvta_generic_to_shared(&Bs[1][0]);

    int KT = K / BKH;
    float acc[2][4][4];
#pragma unroll
    for (int mt = 0; mt < 2; mt++)
#pragma unroll
        for (int nt = 0; nt < 4; nt++)
#pragma unroll
            for (int j = 0; j < 4; j++) acc[mt][nt][j] = 0.f;

    auto load_tile = [&](int buf, int k0) {
#pragma unroll
        for (int t = 0; t < 2; t++) {
            int c = tid + t * 256;
            int r = c >> 2, cc = c & 3;
            int grow = row0 + r;
            int ok = grow < M;
            const __half* src = A + (size_t)(ok ? grow : 0) * K + k0 + cc * 8;
            cp16(sA[buf] + r * (APD * 4) + cc * 16, src, ok);
        }
        int r = tid >> 2, cc = tid & 3;
        const __half* bsrc = Bw + (size_t)(col0 + r) * K + k0 + cc * 8;
        cp16(sB[buf] + r * (APD * 4) + cc * 16, bsrc, 1);
    };

    load_tile(0, 0);
    cp_commit();

    for (int kt = 0; kt < KT; kt++) {
        int buf = kt & 1;
        if (kt + 1 < KT) {
            load_tile(buf ^ 1, (kt + 1) * BKH);
            cp_commit();
            cp_wait<1>();
        } else {
            cp_wait<0>();
        }
        __syncthreads();

        const __half2* Ab = &As[buf][0];
        const __half2* Bb = &Bs[buf][0];
#pragma unroll
        for (int kk = 0; kk < 2; kk++) {
            int kb = kk * 8;
            uint32_t a[2][4];
#pragma unroll
            for (int mt = 0; mt < 2; mt++) {
                int r = wm + mt * 16 + gid;
                a[mt][0] = *reinterpret_cast<const uint32_t*>(&Ab[r * APD + kb + tig]);
                a[mt][1] = *reinterpret_cast<const uint32_t*>(&Ab[(r + 8) * APD + kb + tig]);
                a[mt][2] = *reinterpret_cast<const uint32_t*>(&Ab[r * APD + kb + tig + 4]);
                a[mt][3] = *reinterpret_cast<const uint32_t*>(&Ab[(r + 8) * APD + kb + tig + 4]);
            }
#pragma unroll
            for (int nt = 0; nt < 4; nt++) {
                int n = wn + nt * 8 + gid;
                uint32_t b0 = *reinterpret_cast<const uint32_t*>(&Bb[n * APD + kb + tig]);
                uint32_t b1 = *reinterpret_cast<const uint32_t*>(&Bb[n * APD + kb + tig + 4]);
#pragma unroll
                for (int mt = 0; mt < 2; mt++)
                    mma_f16(acc[mt][nt], a[mt][0], a[mt][1], a[mt][2], a[mt][3], b0, b1);
            }
        }
        __syncthreads();
    }

    // ---- epilogue: fp16 feature store + fused attention-score reduce ----
    int Fh = F >> 1;
#pragma unroll
    for (int mt = 0; mt < 2; mt++) {
        float pS0 = 0.f, pD0 = 0.f, pS1 = 0.f, pD1 = 0.f;
#pragma unroll
        for (int nt = 0; nt < 4; nt++) {
            int cl = wn + nt * 8 + tig * 2;
            int c = col0 + cl;
            float a0s = avS[hh * DHD + cl], a1s = avS[hh * DHD + cl + 1];
            float a0d = avD[hh * DHD + cl], a1d = avD[hh * DHD + cl + 1];
            int r = row0 + wm + mt * 16 + gid;
            if (r < M)
                g_hh[(size_t)r * Fh + (c >> 1)] =
                    __floats2half2_rn(acc[mt][nt][0], acc[mt][nt][1]);
            pS0 += acc[mt][nt][0] * a0s + acc[mt][nt][1] * a1s;
            pD0 += acc[mt][nt][0] * a0d + acc[mt][nt][1] * a1d;
            int r2 = r + 8;
            if (r2 < M)
                g_hh[(size_t)r2 * Fh + (c >> 1)] =
                    __floats2half2_rn(acc[mt][nt][2], acc[mt][nt][3]);
            pS1 += acc[mt][nt][2] * a0s + acc[mt][nt][3] * a1s;
            pD1 += acc[mt][nt][2] * a0d + acc[mt][nt][3] * a1d;
        }
        int rl = wm + mt * 16 + gid;
        atomicAdd(&sS[rl], pS0);
        atomicAdd(&sD[rl], pD0);
        atomicAdd(&sS[rl + 8], pS1);
        atomicAdd(&sD[rl + 8], pD1);
    }
    __syncthreads();
    if (tid < BM) {
        int r = row0 + tid;
        if (r < M) {
            g_ssrc[r * heads + hh] = sS[tid];
            g_sdst[r * heads + hh] = sD[tid];
        }
    }
}

// ------- fused softmax + aggregation, 8 heads, block per node, smem scores -------
// blocks 0/1 also zero BN accumulators (safe: previous layer's bn_apply is done)
__global__ __launch_bounds__(256) void gat_softagg8(const float* __restrict__ bias) {
    __shared__ int   ssm[MAXDEG];
    __shared__ float esm[8 * PADDEG];     // [head][edge]
    __shared__ float sd_sm[8];
    int n = blockIdx.x;
    int tid = threadIdx.x, lane = tid & 31, wid = tid >> 5;   // wid = head
    int half = lane >> 4, l16 = lane & 15;

    if (n == 0) {
        for (int f = tid; f < FH; f += 256) g_sum[f] = 0.0;
    } else if (n == 1) {
        for (int f = tid; f < FH; f += 256) g_sumsq[f] = 0.0;
    }

    int beg = g_rowptr[n];
    int deg = g_rowptr[n + 1] - beg;

    if (deg <= MAXDEG) {
        if (tid < 8) sd_sm[tid] = g_sdst[n * 8 + tid];
        for (int i = tid; i < deg; i += 256) ssm[i] = g_esrc[beg + i];
        __syncthreads();
        for (int i = tid; i < deg * 8; i += 256) {
            int e = i >> 3, h = i & 7;
            float v = g_ssrc[ssm[e] * 8 + h] + sd_sm[h];
            v = v > 0.f ? v : 0.2f * v;
            esm[h * PADDEG + e] = v;
        }
        __syncthreads();
        float* ep = &esm[wid * PADDEG];
        float m = -1e30f;
        for (int i = lane; i < deg; i += 32) m = fmaxf(m, ep[i]);
#pragma unroll
        for (int o = 16; o; o >>= 1) m = fmaxf(m, __shfl_xor_sync(0xffffffffu, m, o));
        float sum = 0.f;
        for (int i = lane; i < deg; i += 32) {
            float ex = __expf(ep[i] - m);
            ep[i] = ex;
            sum += ex;
        }
#pragma unroll
        for (int o = 16; o; o >>= 1) sum += __shfl_xor_sync(0xffffffffu, sum, o);
        float inv = 1.f / (sum + 1e-16f);
        __syncwarp();
        float a0 = 0.f, a1 = 0.f, a2 = 0.f, a3 = 0.f;
#pragma unroll 2
        for (int i = half; i < deg; i += 2) {
            int s = ssm[i];
            float al = ep[i];
            const uint2 u = *reinterpret_cast<const uint2*>(
                &g_hh[(size_t)s * 256 + wid * 32 + l16 * 2]);
            float2 v0 = __half22float2(*reinterpret_cast<const __half2*>(&u.x));
            float2 v1 = __half22float2(*reinterpret_cast<const __half2*>(&u.y));
            a0 += al * v0.x; a1 += al * v0.y;
            a2 += al * v1.x; a3 += al * v1.y;
        }
        a0 += __shfl_xor_sync(0xffffffffu, a0, 16);
        a1 += __shfl_xor_sync(0xffffffffu, a1, 16);
        a2 += __shfl_xor_sync(0xffffffffu, a2, 16);
        a3 += __shfl_xor_sync(0xffffffffu, a3, 16);
        if (half == 0) {
            int cb = wid * DHD + l16 * 4;
            float4 o;
            o.x = a0 * inv + bias[cb];
            o.y = a1 * inv + bias[cb + 1];
            o.z = a2 * inv + bias[cb + 2];
            o.w = a3 * inv + bias[cb + 3];
            *reinterpret_cast<float4*>(&g_agg[(size_t)n * FH + cb]) = o;
        }
    } else {
        float sd = g_sdst[n * 8 + wid];
        float* ap = g_alpha + (size_t)wid * ET;
        float m = -1e30f;
        for (int i = beg + lane; i < beg + deg; i += 32) {
            int s = g_esrc[i];
            float e = g_ssrc[s * 8 + wid] + sd;
            e = e > 0.f ? e : 0.2f * e;
            ap[i] = e;
            m = fmaxf(m, e);
        }
#pragma unroll
        for (int o = 16; o; o >>= 1) m = fmaxf(m, __shfl_xor_sync(0xffffffffu, m, o));
        float sum = 0.f;
        for (int i = beg + lane; i < beg + deg; i += 32) {
            float e = __expf(ap[i] - m);
            ap[i] = e;
            sum += e;
        }
#pragma unroll
        for (int o = 16; o; o >>= 1) sum += __shfl_xor_sync(0xffffffffu, sum, o);
        float inv = 1.f / (sum + 1e-16f);
        float ax = 0.f, ay = 0.f;
        for (int i = beg; i < beg + deg; i++) {
            int s = g_esrc[i];
            float al = ap[i];
            float2 v = __half22float2(g_hh[(size_t)s * 256 + wid * 32 + lane]);
            ax += al * v.x;
            ay += al * v.y;
        }
        size_t o = (size_t)n * FH + wid * DHD + 2 * lane;
        g_agg[o]     = ax * inv + bias[wid * DHD + 2 * lane];
        g_agg[o + 1] = ay * inv + bias[wid * DHD + 2 * lane + 1];
    }
}

// ---------------- single-head softmax+agg (layer 2), warp per node ----------------
__global__ void gat_softagg1(const float* __restrict__ bias) {
    if (blockIdx.x == 0 && threadIdx.y == 0) {
        for (int f = threadIdx.x; f < DHD; f += 32) { g_sum[f] = 0.0; g_sumsq[f] = 0.0; }
    }
    int n = blockIdx.x * blockDim.y + threadIdx.y;
    if (n >= NN) return;
    int lane = threadIdx.x;
    int half = lane >> 4, l16 = lane & 15;
    int beg = g_rowptr[n], end = g_rowptr[n + 1];
    float sd = g_sdst[n];
    float* ap = g_alpha;

    float m = -1e30f;
    for (int i = beg + lane; i < end; i += 32) {
        int s = g_esrc[i];
        float e = g_ssrc[s] + sd;
        e = e > 0.f ? e : 0.2f * e;
        ap[i] = e;
        m = fmaxf(m, e);
    }
#pragma unroll
    for (int o = 16; o; o >>= 1) m = fmaxf(m, __shfl_xor_sync(0xffffffffu, m, o));
    float sum = 0.f;
    for (int i = beg + lane; i < end; i += 32) {
        float e = __expf(ap[i] - m);
        ap[i] = e;
        sum += e;
    }
#pragma unroll
    for (int o = 16; o; o >>= 1) sum += __shfl_xor_sync(0xffffffffu, sum, o);
    float inv = 1.f / (sum + 1e-16f);

    float a0 = 0.f, a1 = 0.f, a2 = 0.f, a3 = 0.f;
#pragma unroll 2
    for (int i = beg + half; i < end; i += 2) {
        int s = g_esrc[i];
        float al = ap[i];
        const uint2 u = *reinterpret_cast<const uint2*>(&g_hh[(size_t)s * 32 + l16 * 2]);
        float2 v0 = __half22float2(*reinterpret_cast<const __half2*>(&u.x));
        float2 v1 = __half22float2(*reinterpret_cast<const __half2*>(&u.y));
        a0 += al * v0.x; a1 += al * v0.y;
        a2 += al * v1.x; a3 += al * v1.y;
    }
    a0 += __shfl_xor_sync(0xffffffffu, a0, 16);
    a1 += __shfl_xor_sync(0xffffffffu, a1, 16);
    a2 += __shfl_xor_sync(0xffffffffu, a2, 16);
    a3 += __shfl_xor_sync(0xffffffffu, a3, 16);
    if (half == 0) {
        int cb = l16 * 4;
        float4 o;
        o.x = a0 * inv + bias[cb];
        o.y = a1 * inv + bias[cb + 1];
        o.z = a2 * inv + bias[cb + 2];
        o.w = a3 * inv + bias[cb + 3];
        *reinterpret_cast<float4*>(&g_agg[(size_t)n * DHD + cb]) = o;
    }
}

// ---------------- batch norm ----------------
__global__ void bn_stats(int F) {
    int r0 = blockIdx.x * 64;
    int rend = min(r0 + 64, NN);
    for (int f = threadIdx.x; f < F; f += blockDim.x) {
        float s = 0.f, q = 0.f;
        for (int r = r0; r < rend; r++) {
            float v = g_agg[(size_t)r * F + f];
            s += v; q += v * v;
        }
        atomicAdd(&g_sum[f], (double)s);
        atomicAdd(&g_sumsq[f], (double)q);
    }
}

__global__ void bn_apply(const float* __restrict__ gw, const float* __restrict__ bw,
                         int F, int outsel, int useResid, int writeHalf, int zeroPool) {
    if (zeroPool && blockIdx.x == 0) {
        for (int i = threadIdx.x; i < GG * DHD; i += 256) g_pool[i] = 0.f;
        if (threadIdx.x < GG) g_cnt[threadIdx.x] = 0;
    }
    size_t i4 = (size_t)blockIdx.x * blockDim.x + threadIdx.x;
    size_t total4 = (size_t)NN * F / 4;
    if (i4 >= total4) return;
    size_t i = i4 * 4;
    int f = (int)(i % F);
    float4 v = *reinterpret_cast<const float4*>(g_agg + i);
    float* vv = &v.x;
    float4 o;
    float* oo = &o.x;
#pragma unroll
    for (int j = 0; j < 4; j++) {
        int fj = f + j;
        float mean = (float)(g_sum[fj] * (1.0 / NN));
        float var  = (float)(g_sumsq[fj] * (1.0 / NN)) - mean * mean;
        float y = (vv[j] - mean) * rsqrtf(var + 1e-5f) * gw[fj] + bw[fj];
        oo[j] = y > 0.f ? y : expm1f(y);
    }
    if (useResid) {
        float4 rr = *reinterpret_cast<const float4*>(g_x1 + i);
        o.x += rr.x; o.y += rr.y; o.z += rr.z; o.w += rr.w;
    }
    *reinterpret_cast<float4*>(sel_buf(outsel) + i) = o;
    if (writeHalf) {
        __half2* hp = reinterpret_cast<__half2*>(g_ah);
        hp[i / 2]     = __floats2half2_rn(o.x, o.y);
        hp[i / 2 + 1] = __floats2half2_rn(o.z, o.w);
    }
}

// ---------------- layer norm + global mean pool ----------------
__global__ void ln_pool(const float* __restrict__ lg, const float* __restrict__ lb,
                        const void* __restrict__ batch) {
    int n = blockIdx.x * blockDim.y + threadIdx.y;
    if (n >= NN) return;
    int lane = threadIdx.x;
    float v0 = g_x1[(size_t)n * 64 + lane], v1 = g_x1[(size_t)n * 64 + lane + 32];
    float s = v0 + v1;
#pragma unroll
    for (int o = 16; o; o >>= 1) s += __shfl_xor_sync(0xffffffffu, s, o);
    float mean = s * (1.f / 64.f);
    float d0 = v0 - mean, d1 = v1 - mean;
    float q = d0 * d0 + d1 * d1;
#pragma unroll
    for (int o = 16; o; o >>= 1) q += __shfl_xor_sync(0xffffffffu, q, o);
    float r = rsqrtf(q * (1.f / 64.f) + 1e-5f);
    float y0 = d0 * r * lg[lane] + lb[lane];
    float y1 = d1 * r * lg[lane + 32] + lb[lane + 32];
    int g = idx_at(batch, (size_t)n);
    atomicAdd(&g_pool[g * 64 + lane], y0);
    atomicAdd(&g_pool[g * 64 + lane + 32], y1);
    if (lane == 0) atomicAdd(&g_cnt[g], 1);
}

// ---------------- MLP head + log_softmax ----------------
__global__ void head_kernel(const float* __restrict__ fc1w, const float* __restrict__ fc1b,
                            const float* __restrict__ fc2w, const float* __restrict__ fc2b,
                            float* __restrict__ out) {
    int t = threadIdx.x;
    if (t >= GG) return;
    float inv = 1.f / fmaxf((float)g_cnt[t], 1.f);
    float p[64];
#pragma unroll
    for (int f = 0; f < 64; f++) p[f] = g_pool[t * 64 + f] * inv;
    float l0 = fc2b[0], l1 = fc2b[1];
    for (int j = 0; j < 32; j++) {
        float s = fc1b[j];
#pragma unroll
        for (int f = 0; f < 64; f++) s += p[f] * fc1w[f * 32 + j];
        s = s > 0.f ? s : expm1f(s);
        l0 += s * fc2w[j * 2 + 0];
        l1 += s * fc2w[j * 2 + 1];
    }
    float mx = fmaxf(l0, l1);
    float lse = mx + logf(expf(l0 - mx) + expf(l1 - mx));
    out[t * 2 + 0] = l0 - lse;
    out[t * 2 + 1] = l1 - lse;
}

// ---------------- launch ----------------
extern "C" void kernel_launch(void* const* d_in, const int* in_sizes, int n_in,
                              void* d_out, int out_size) {
    const float* x     = (const float*)d_in[0];
    const void*  ei    = d_in[1];
    const void*  batch = d_in[2];
    const float *W0 = (const float*)d_in[3],  *as0 = (const float*)d_in[4],
                *ad0 = (const float*)d_in[5], *b0  = (const float*)d_in[6];
    const float *W1 = (const float*)d_in[7],  *as1 = (const float*)d_in[8],
                *ad1 = (const float*)d_in[9], *b1  = (const float*)d_in[10];
    const float *W2 = (const float*)d_in[11], *as2 = (const float*)d_in[12],
                *ad2 = (const float*)d_in[13], *b2 = (const float*)d_in[14];
    const float *bn0g = (const float*)d_in[15], *bn0b = (const float*)d_in[16];
    const float *bn1g = (const float*)d_in[17], *bn1b = (const float*)d_in[18];
    const float *bn2g = (const float*)d_in[19], *bn2b = (const float*)d_in[20];
    const float *lng  = (const float*)d_in[21], *lnb  = (const float*)d_in[22];
    const float *fc1w = (const float*)d_in[23], *fc1b = (const float*)d_in[24];
    const float *fc2w = (const float*)d_in[25], *fc2b = (const float*)d_in[26];
    float* out = (float*)d_out;

    static cudaStream_t s2 = 0;
    static cudaEvent_t evFork = 0, evJoin = 0;
    static int inited = 0;
    if (!inited) {
        cudaStreamCreateWithFlags(&s2, cudaStreamNonBlocking);
        cudaEventCreateWithFlags(&evFork, cudaEventDisableTiming);
        cudaEventCreateWithFlags(&evJoin, cudaEventDisableTiming);
        inited = 1;
    }

    int gm = (NN + BM - 1) / BM;
    int bnStatGrid = (NN + 63) / 64;

    cudaEventRecord(evFork, 0);
    cudaStreamWaitEvent(s2, evFork, 0);

    cvt_x<<<(NN * 256 / 4 + 255) / 256, 256>>>(x);                 // 1 (main)
    cvt_w<<<(256 * 512 + 255) / 256, 256>>>(W0, 0, 256, 512);      // 2 (main)
    detect_dtype<<<1, 256, 0, s2>>>(ei);                           // 3 (s2)
    gemm_fp16<<<dim3(FH / BN, gm), 256>>>(0, as0, ad0, NN, 256, FH, 8);  // 4 (main)

    csr_init   <<<(NN + 255) / 256, 256, 0, s2>>>();
    csr_count  <<<(EE + 255) / 256, 256, 0, s2>>>(ei);
    cvt_w      <<<(512 * 512 + 255) / 256, 256, 0, s2>>>(W1, 1, 512, 512);
    cvt_w      <<<(512 * 64 + 255) / 256, 256, 0, s2>>>(W2, 2, 512, 64);
    csr_scan   <<<1, 1024, 0, s2>>>();
    csr_scatter<<<(ET + 255) / 256, 256, 0, s2>>>(ei);
    cudaEventRecord(evJoin, s2);
    cudaStreamWaitEvent(0, evJoin, 0);

    // --- layer 0 ---
    gat_softagg8<<<NN, 256>>>(b0);
    bn_stats <<<bnStatGrid, 256>>>(FH);
    bn_apply <<<(int)(((size_t)NN * FH / 4 + 255) / 256), 256>>>(bn0g, bn0b, FH, 1, 0, 1, 0);

    // --- layer 1: residual ---
    gemm_fp16<<<dim3(FH / BN, gm), 256>>>(1, as1, ad1, NN, FH, FH, 8);
    gat_softagg8<<<NN, 256>>>(b1);
    bn_stats <<<bnStatGrid, 256>>>(FH);
    bn_apply <<<(int)(((size_t)NN * FH / 4 + 255) / 256), 256>>>(bn1g, bn1b, FH, 2, 1, 1, 0);

    // --- layer 2: single head ---
    gemm_fp16<<<dim3(1, gm), 256>>>(2, as2, ad2, NN, FH, DHD, 1);
    gat_softagg1<<<(NN + 7) / 8, dim3(32, 8)>>>(b2);
    bn_stats <<<bnStatGrid, 256>>>(DHD);
    bn_apply <<<(int)(((size_t)NN * DHD / 4 + 255) / 256), 256>>>(bn2g, bn2b, DHD, 1, 0, 0, 1);

    // --- layer norm + pool + head ---
    ln_pool<<<(NN + 7) / 8, dim3(32, 8)>>>(lng, lnb, batch);
    head_kernel<<<1, 32>>>(fc1w, fc1b, fc2w, fc2b, out);
}